// round 3
// baseline (speedup 1.0000x reference)
#include <cuda_runtime.h>

#define BDIM 8
#define CDIM 256
#define LDIM 1024
#define NH 8
#define DK 32
#define TABLE 3969   // 63*63
#define BQ 64
#define BKT 64

// Scratch (device globals: allocation-free rule)
__device__ float g_q[BDIM*NH*LDIM*DK];     // [b][h][l][d]
__device__ float g_k[BDIM*NH*LDIM*DK];
__device__ float g_v[BDIM*NH*LDIM*DK];
__device__ float g_o[BDIM*LDIM*CDIM];      // [b][l][h*32+d]

// ---------------------------------------------------------------------------
// K1: QKV projection.  xf(1024x256) @ W(256x256) per batch, N=768 fused.
// grid (12 n-tiles, 16 l-tiles, 8 b), 256 threads, 64x64 tile, 4x4 micro.
// ---------------------------------------------------------------------------
__global__ __launch_bounds__(256)
void qkv_kernel(const float* __restrict__ x, const float* __restrict__ Qw,
                const float* __restrict__ Kw, const float* __restrict__ Vw) {
    __shared__ float As[32][65];   // [c][l]
    __shared__ float Bs[32][65];   // [c][n]
    int b  = blockIdx.z;
    int l0 = blockIdx.y * 64;
    int n0g = blockIdx.x * 64;
    const float* W; float* dst; int n0;
    if (n0g < 256)      { W = Qw; dst = g_q; n0 = n0g; }
    else if (n0g < 512) { W = Kw; dst = g_k; n0 = n0g - 256; }
    else                { W = Vw; dst = g_v; n0 = n0g - 512; }

    const float* xb = x + b * CDIM * LDIM;
    int tx = threadIdx.x & 15;   // n dim
    int ty = threadIdx.x >> 4;   // l dim
    float acc[4][4];
#pragma unroll
    for (int i = 0; i < 4; i++)
#pragma unroll
        for (int j = 0; j < 4; j++) acc[i][j] = 0.f;

    for (int c0 = 0; c0 < CDIM; c0 += 32) {
        for (int i = threadIdx.x; i < 32 * 64; i += 256) {
            int ll = i & 63, cc = i >> 6;
            As[cc][ll] = xb[(c0 + cc) * LDIM + l0 + ll];
            Bs[cc][i & 63] = W[(c0 + cc) * 256 + n0 + (i & 63)];
        }
        __syncthreads();
#pragma unroll 8
        for (int cc = 0; cc < 32; cc++) {
            float a[4], bb[4];
#pragma unroll
            for (int i = 0; i < 4; i++) a[i]  = As[cc][ty + 16 * i];
#pragma unroll
            for (int j = 0; j < 4; j++) bb[j] = Bs[cc][tx + 16 * j];
#pragma unroll
            for (int i = 0; i < 4; i++)
#pragma unroll
                for (int j = 0; j < 4; j++) acc[i][j] += a[i] * bb[j];
        }
        __syncthreads();
    }
#pragma unroll
    for (int i = 0; i < 4; i++) {
        int l = l0 + ty + 16 * i;
#pragma unroll
        for (int j = 0; j < 4; j++) {
            int n = n0 + tx + 16 * j;
            dst[((b * NH + (n >> 5)) * LDIM + l) * DK + (n & 31)] = acc[i][j];
        }
    }
}

// ---------------------------------------------------------------------------
// K2: flash attention with analytic relative bias.
// Block: (b, h, 64 q-rows), 256 threads (8 warps, 8 q-rows each).
// Key blocks of 64. Bias index computed closed-form (no rel_idx reads).
// ---------------------------------------------------------------------------
__global__ __launch_bounds__(256)
void attn_kernel(const float* __restrict__ rel_bias) {
    __shared__ float qs[BQ][33];
    __shared__ float ks[BKT][33];
    __shared__ float vs[BKT][33];
    __shared__ float ss[BQ][65];

    int b  = blockIdx.z;
    int h  = blockIdx.y;
    int l0 = blockIdx.x * BQ;
    int tid  = threadIdx.x;
    int lane = tid & 31, w = tid >> 5;
    int tx = tid & 15, ty = tid >> 4;

    const float* qp = g_q + (b * NH + h) * LDIM * DK;
    const float* kp = g_k + (b * NH + h) * LDIM * DK;
    const float* vp = g_v + (b * NH + h) * LDIM * DK;
    const float* bias = rel_bias + h * TABLE;

    for (int i = tid; i < BQ * DK; i += 256) {
        int r = i >> 5, d = i & 31;
        qs[r][d] = qp[(l0 + r) * DK + d];
    }

    float m[8], lsum[8], o[8];
#pragma unroll
    for (int rr = 0; rr < 8; rr++) { m[rr] = -1e30f; lsum[rr] = 0.f; o[rr] = 0.f; }

    for (int kb = 0; kb < LDIM; kb += BKT) {
        __syncthreads();   // prior O-update done before overwriting ks/vs
        for (int i = tid; i < BKT * DK; i += 256) {
            int r = i >> 5, d = i & 31;
            ks[r][d] = kp[(kb + r) * DK + d];
            vs[r][d] = vp[(kb + r) * DK + d];
        }
        __syncthreads();

        // S = q @ k^T + bias  (64x64 tile, 4x4 micro per thread)
        float acc[4][4];
#pragma unroll
        for (int i = 0; i < 4; i++)
#pragma unroll
            for (int j = 0; j < 4; j++) acc[i][j] = 0.f;
#pragma unroll 8
        for (int d = 0; d < 32; d++) {
            float aq[4], bk[4];
#pragma unroll
            for (int i = 0; i < 4; i++) aq[i] = qs[ty + 16 * i][d];
#pragma unroll
            for (int j = 0; j < 4; j++) bk[j] = ks[tx + 16 * j][d];
#pragma unroll
            for (int i = 0; i < 4; i++)
#pragma unroll
                for (int j = 0; j < 4; j++) acc[i][j] += aq[i] * bk[j];
        }
#pragma unroll
        for (int i = 0; i < 4; i++) {
            int qi = l0 + ty + 16 * i;
            int yi = qi >> 5, xi = qi & 31;
#pragma unroll
            for (int j = 0; j < 4; j++) {
                int kj = kb + tx + 16 * j;
                int yj = kj >> 5, xj = kj & 31;
                int idx = ((yj - yi + 32) << 5) + (xj - xi + 32);
                ss[ty + 16 * i][tx + 16 * j] = acc[i][j] + __ldg(&bias[idx]);
            }
        }
        __syncthreads();

        // online softmax: warp w owns rows w*8 .. w*8+7
#pragma unroll
        for (int rr = 0; rr < 8; rr++) {
            int r = w * 8 + rr;
            float p0 = ss[r][lane];
            float p1 = ss[r][lane + 32];
            float mx = fmaxf(p0, p1);
#pragma unroll
            for (int s = 16; s > 0; s >>= 1)
                mx = fmaxf(mx, __shfl_xor_sync(0xffffffffu, mx, s));
            float mnew = fmaxf(m[rr], mx);
            p0 = __expf(p0 - mnew);
            p1 = __expf(p1 - mnew);
            ss[r][lane]      = p0;
            ss[r][lane + 32] = p1;
            float psum = p0 + p1;
#pragma unroll
            for (int s = 16; s > 0; s >>= 1)
                psum += __shfl_xor_sync(0xffffffffu, psum, s);
            float corr = __expf(m[rr] - mnew);
            lsum[rr] = lsum[rr] * corr + psum;
            o[rr] *= corr;
            m[rr] = mnew;
        }
        __syncwarp();

        // O += P @ V : lane owns dim = lane
#pragma unroll 4
        for (int j = 0; j < BKT; j++) {
            float vv = vs[j][lane];
#pragma unroll
            for (int rr = 0; rr < 8; rr++)
                o[rr] += ss[w * 8 + rr][j] * vv;
        }
    }

#pragma unroll
    for (int rr = 0; rr < 8; rr++) {
        int l = l0 + w * 8 + rr;
        g_o[(b * LDIM + l) * CDIM + h * DK + lane] = o[rr] / lsum[rr];
    }
}

// ---------------------------------------------------------------------------
// K3: FF GEMM + bias + transpose.  out[b][oc][l] = g_o[b,l,:]@ffw[:,oc]+ffb.
// grid (4 oc-tiles, 16 l-tiles, 8 b). l mapped to tx for coalesced stores.
// ---------------------------------------------------------------------------
__global__ __launch_bounds__(256)
void ff_kernel(const float* __restrict__ ffw, const float* __restrict__ ffb,
               float* __restrict__ out) {
    __shared__ float As[32][65];   // [c][l]
    __shared__ float Bs[32][65];   // [c][oc]
    int b  = blockIdx.z;
    int l0 = blockIdx.y * 64;
    int n0 = blockIdx.x * 64;
    int tx = threadIdx.x & 15;   // l dim
    int ty = threadIdx.x >> 4;   // oc dim
    const float* A = g_o + b * LDIM * CDIM;

    float acc[4][4];
#pragma unroll
    for (int i = 0; i < 4; i++)
#pragma unroll
        for (int j = 0; j < 4; j++) acc[i][j] = 0.f;

    for (int c0 = 0; c0 < CDIM; c0 += 32) {
        for (int i = threadIdx.x; i < 32 * 64; i += 256) {
            int ll = i >> 5, cc = i & 31;
            As[cc][ll] = A[(l0 + ll) * CDIM + c0 + cc];
            int nn = i & 63, cc2 = i >> 6;
            Bs[cc2][nn] = ffw[(c0 + cc2) * 256 + n0 + nn];
        }
        __syncthreads();
#pragma unroll 8
        for (int cc = 0; cc < 32; cc++) {
            float a[4], bb[4];
#pragma unroll
            for (int i = 0; i < 4; i++) a[i]  = As[cc][tx + 16 * i];
#pragma unroll
            for (int j = 0; j < 4; j++) bb[j] = Bs[cc][ty + 16 * j];
#pragma unroll
            for (int i = 0; i < 4; i++)
#pragma unroll
                for (int j = 0; j < 4; j++) acc[i][j] += a[i] * bb[j];
        }
        __syncthreads();
    }
#pragma unroll
    for (int j = 0; j < 4; j++) {
        int oc = n0 + ty + 16 * j;
        float bv = ffb[oc];
        float* orow = out + (b * 256 + oc) * LDIM + l0;
#pragma unroll
        for (int i = 0; i < 4; i++)
            orow[tx + 16 * i] = acc[i][j] + bv;
    }
}

extern "C" void kernel_launch(void* const* d_in, const int* in_sizes, int n_in,
                              void* d_out, int out_size) {
    const float* x        = (const float*)d_in[0];
    const float* Qw       = (const float*)d_in[1];
    const float* Kw       = (const float*)d_in[2];
    const float* Vw       = (const float*)d_in[3];
    const float* ffw      = (const float*)d_in[4];
    const float* ffb      = (const float*)d_in[5];
    const float* rel_bias = (const float*)d_in[6];
    // d_in[7] = rel_idx : reproduced analytically in-kernel, not read.
    float* out = (float*)d_out;

    qkv_kernel<<<dim3(12, 16, 8), 256>>>(x, Qw, Kw, Vw);
    attn_kernel<<<dim3(16, 8, 8), 256>>>(rel_bias);
    ff_kernel<<<dim3(4, 16, 8), 256>>>(ffw, ffb, out);
}

// round 13
// speedup vs baseline: 2.8096x; 2.8096x over previous
#include <cuda_runtime.h>
#include <cuda_fp16.h>

#define LDIM 1024
#define CDIM 256
#define NH 8

// Scratch planes (allocation-free rule). hi/lo fp16 split = fp32-accurate mma.
__device__ __half g_qh[8*NH*LDIM*32];
__device__ __half g_ql[8*NH*LDIM*32];
__device__ __half g_kh[8*NH*LDIM*32];
__device__ __half g_kl[8*NH*LDIM*32];
__device__ __half g_vh[8*NH*32*LDIM];   // [b][h][d][l] (transposed for PV B-operand)
__device__ __half g_vl[8*NH*32*LDIM];
__device__ __half g_oh[8*LDIM*CDIM];    // [b][l][c]
__device__ __half g_ol[8*LDIM*CDIM];

__device__ __forceinline__ void mma16816(float* d, const unsigned* a,
                                         unsigned b0, unsigned b1) {
    asm volatile(
        "mma.sync.aligned.m16n8k16.row.col.f32.f16.f16.f32 "
        "{%0,%1,%2,%3},{%4,%5,%6,%7},{%8,%9},{%0,%1,%2,%3};"
        : "+f"(d[0]), "+f"(d[1]), "+f"(d[2]), "+f"(d[3])
        : "r"(a[0]), "r"(a[1]), "r"(a[2]), "r"(a[3]), "r"(b0), "r"(b1));
}

__device__ __forceinline__ unsigned ldu32(const __half* p) {
    return *reinterpret_cast<const unsigned*>(p);
}
__device__ __forceinline__ unsigned packf2(float a, float b) {
    __half2 t = __floats2half2_rn(a, b);
    return *reinterpret_cast<unsigned*>(&t);
}
__device__ __forceinline__ void splitf(float f, __half& h, __half& l) {
    h = __float2half_rn(f);
    l = __float2half_rn(f - __half2float(h));
}

// ---------------------------------------------------------------------------
// K1: QKV projection via split-fp16 mma. grid(12,16,8) x 256 thr.
// m=l (64), n=out-channel (64), k=c. 8 warps: 4(m) x 2(n), warp tile 16x32.
// ---------------------------------------------------------------------------
__global__ __launch_bounds__(256)
void qkv_kernel(const float* __restrict__ x, const float* __restrict__ Qw,
                const float* __restrict__ Kw, const float* __restrict__ Vw) {
    __shared__ __half Xh[64][40], Xl[64][40];   // [l][c-chunk]
    __shared__ __half Wh[64][40], Wl[64][40];   // [n][c-chunk]
    int b = blockIdx.z, l0 = blockIdx.y * 64, n0g = blockIdx.x * 64;
    const float* W; int which, n0;
    if (n0g < 256)      { W = Qw; which = 0; n0 = n0g; }
    else if (n0g < 512) { W = Kw; which = 1; n0 = n0g - 256; }
    else                { W = Vw; which = 2; n0 = n0g - 512; }
    const float* xb = x + b * CDIM * LDIM;
    int tid = threadIdx.x, lane = tid & 31, w = tid >> 5;
    int g = lane >> 2, tig = lane & 3;
    int wm = (w & 3) * 16, wn = (w >> 2) * 32;

    float acc[4][4];
#pragma unroll
    for (int i = 0; i < 4; i++)
#pragma unroll
        for (int j = 0; j < 4; j++) acc[i][j] = 0.f;

    for (int c0 = 0; c0 < 256; c0 += 32) {
        __syncthreads();
        for (int i = tid; i < 64 * 32; i += 256) {
            int ll = i & 63, cc = i >> 6;
            splitf(xb[(c0 + cc) * LDIM + l0 + ll], Xh[ll][cc], Xl[ll][cc]);
            splitf(W[(c0 + cc) * 256 + n0 + ll], Wh[ll][cc], Wl[ll][cc]);
        }
        __syncthreads();
#pragma unroll
        for (int kc = 0; kc < 32; kc += 16) {
            unsigned ah[4], al[4];
            ah[0] = ldu32(&Xh[wm + g][kc + 2 * tig]);
            ah[1] = ldu32(&Xh[wm + g + 8][kc + 2 * tig]);
            ah[2] = ldu32(&Xh[wm + g][kc + 2 * tig + 8]);
            ah[3] = ldu32(&Xh[wm + g + 8][kc + 2 * tig + 8]);
            al[0] = ldu32(&Xl[wm + g][kc + 2 * tig]);
            al[1] = ldu32(&Xl[wm + g + 8][kc + 2 * tig]);
            al[2] = ldu32(&Xl[wm + g][kc + 2 * tig + 8]);
            al[3] = ldu32(&Xl[wm + g + 8][kc + 2 * tig + 8]);
#pragma unroll
            for (int nt = 0; nt < 4; nt++) {
                int r = wn + 8 * nt + g;
                unsigned bh0 = ldu32(&Wh[r][kc + 2 * tig]);
                unsigned bh1 = ldu32(&Wh[r][kc + 2 * tig + 8]);
                unsigned bl0 = ldu32(&Wl[r][kc + 2 * tig]);
                unsigned bl1 = ldu32(&Wl[r][kc + 2 * tig + 8]);
                mma16816(acc[nt], ah, bh0, bh1);
                mma16816(acc[nt], ah, bl0, bl1);
                mma16816(acc[nt], al, bh0, bh1);
            }
        }
    }
#pragma unroll
    for (int nt = 0; nt < 4; nt++) {
        int n = n0 + wn + 8 * nt + 2 * tig;
        int h = n >> 5, d = n & 31;
#pragma unroll
        for (int rr = 0; rr < 2; rr++) {
            int r = l0 + wm + g + rr * 8;
            float f0 = acc[nt][rr * 2], f1 = acc[nt][rr * 2 + 1];
            __half h0, e0, h1, e1;
            splitf(f0, h0, e0); splitf(f1, h1, e1);
            if (which == 2) {
                int vi = ((b * NH + h) * 32 + d) * LDIM + r;
                g_vh[vi] = h0; g_vh[vi + LDIM] = h1;
                g_vl[vi] = e0; g_vl[vi + LDIM] = e1;
            } else {
                int qi = ((b * NH + h) * LDIM + r) * 32 + d;
                __half* hp = which ? g_kh : g_qh;
                __half* lp = which ? g_kl : g_ql;
                *reinterpret_cast<__half2*>(hp + qi) = __halves2half2(h0, h1);
                *reinterpret_cast<__half2*>(lp + qi) = __halves2half2(e0, e1);
            }
        }
    }
}

// ---------------------------------------------------------------------------
// K2: flash attention, split-fp16 S = QK^T (exact), fp16 P @ split V.
// grid(16 qtile, 8 h, 8 b) x 128 thr (4 warps, warp = 16 q rows).
// Bias: idx = j - qi + 1056 (linear!) -> 128-float smem strip per k-block.
// ---------------------------------------------------------------------------
__global__ __launch_bounds__(128)
void attn_kernel(const float* __restrict__ rel_bias) {
    __shared__ __half Kh[64][40], Kl[64][40];   // [j][d]
    __shared__ __half Vh[32][72], Vl[32][72];   // [d][j]
    __shared__ float bsb[128];
    int b = blockIdx.z, h = blockIdx.y, l0 = blockIdx.x * 64;
    int tid = threadIdx.x, lane = tid & 31, w = tid >> 5;
    int g = lane >> 2, tig = lane & 3;
    const __half* qhp = g_qh + (b * NH + h) * LDIM * 32;
    const __half* qlp = g_ql + (b * NH + h) * LDIM * 32;
    const __half* khp = g_kh + (b * NH + h) * LDIM * 32;
    const __half* klp = g_kl + (b * NH + h) * LDIM * 32;
    const __half* vhp = g_vh + (b * NH + h) * 32 * LDIM;
    const __half* vlp = g_vl + (b * NH + h) * 32 * LDIM;
    const float* bias = rel_bias + h * 3969;

    int r0 = l0 + w * 16 + g;            // row for c0,c1 ; r0+8 for c2,c3
    // Q fragments held in registers across the whole k loop
    unsigned qfh[2][4], qfl[2][4];
#pragma unroll
    for (int kc = 0; kc < 2; kc++) {
        int c = kc * 16 + 2 * tig;
        qfh[kc][0] = ldu32(qhp + r0 * 32 + c);
        qfh[kc][1] = ldu32(qhp + (r0 + 8) * 32 + c);
        qfh[kc][2] = ldu32(qhp + r0 * 32 + c + 8);
        qfh[kc][3] = ldu32(qhp + (r0 + 8) * 32 + c + 8);
        qfl[kc][0] = ldu32(qlp + r0 * 32 + c);
        qfl[kc][1] = ldu32(qlp + (r0 + 8) * 32 + c);
        qfl[kc][2] = ldu32(qlp + r0 * 32 + c + 8);
        qfl[kc][3] = ldu32(qlp + (r0 + 8) * 32 + c + 8);
    }

    float m0 = -1e30f, m1 = -1e30f, lsum0 = 0.f, lsum1 = 0.f;
    float o[4][4];
#pragma unroll
    for (int i = 0; i < 4; i++)
#pragma unroll
        for (int j = 0; j < 4; j++) o[i][j] = 0.f;

    for (int kb = 0; kb < LDIM; kb += 64) {
        __syncthreads();
        {   // fill K (64x32), V^T (32x64), bias strip
            int rr = tid >> 2, q4 = tid & 3;
#pragma unroll
            for (int rep = 0; rep < 2; rep++) {
                int row = rr + rep * 32;
                *reinterpret_cast<uint4*>(&Kh[row][q4 * 8]) =
                    *reinterpret_cast<const uint4*>(khp + (kb + row) * 32 + q4 * 8);
                *reinterpret_cast<uint4*>(&Kl[row][q4 * 8]) =
                    *reinterpret_cast<const uint4*>(klp + (kb + row) * 32 + q4 * 8);
            }
#pragma unroll
            for (int rep = 0; rep < 2; rep++) {
                int jseg = q4 + rep * 4;
                *reinterpret_cast<uint4*>(&Vh[rr][jseg * 8]) =
                    *reinterpret_cast<const uint4*>(vhp + rr * LDIM + kb + jseg * 8);
                *reinterpret_cast<uint4*>(&Vl[rr][jseg * 8]) =
                    *reinterpret_cast<const uint4*>(vlp + rr * LDIM + kb + jseg * 8);
            }
            bsb[tid] = bias[kb - l0 - 63 + 1056 + tid];
        }
        __syncthreads();

        float s[8][4];
#pragma unroll
        for (int nt = 0; nt < 8; nt++)
#pragma unroll
            for (int j = 0; j < 4; j++) s[nt][j] = 0.f;
#pragma unroll
        for (int kc = 0; kc < 2; kc++) {
#pragma unroll
            for (int nt = 0; nt < 8; nt++) {
                int jr = 8 * nt + g;
                unsigned bh0 = ldu32(&Kh[jr][kc * 16 + 2 * tig]);
                unsigned bh1 = ldu32(&Kh[jr][kc * 16 + 2 * tig + 8]);
                unsigned bl0 = ldu32(&Kl[jr][kc * 16 + 2 * tig]);
                unsigned bl1 = ldu32(&Kl[jr][kc * 16 + 2 * tig + 8]);
                mma16816(s[nt], qfh[kc], bh0, bh1);
                mma16816(s[nt], qfh[kc], bl0, bl1);
                mma16816(s[nt], qfl[kc], bh0, bh1);
            }
        }
        // bias add (linear relative index)
        int ro0 = 63 - (w * 16 + g);
        int ro1 = ro0 - 8;
#pragma unroll
        for (int nt = 0; nt < 8; nt++) {
            int j = 8 * nt + 2 * tig;
            s[nt][0] += bsb[j + ro0]; s[nt][1] += bsb[j + 1 + ro0];
            s[nt][2] += bsb[j + ro1]; s[nt][3] += bsb[j + 1 + ro1];
        }
        // online softmax (rows r0, r0+8), 4-lane groups share a row
        float mx0 = -1e30f, mx1 = -1e30f;
#pragma unroll
        for (int nt = 0; nt < 8; nt++) {
            mx0 = fmaxf(mx0, fmaxf(s[nt][0], s[nt][1]));
            mx1 = fmaxf(mx1, fmaxf(s[nt][2], s[nt][3]));
        }
        mx0 = fmaxf(mx0, __shfl_xor_sync(0xffffffffu, mx0, 1));
        mx0 = fmaxf(mx0, __shfl_xor_sync(0xffffffffu, mx0, 2));
        mx1 = fmaxf(mx1, __shfl_xor_sync(0xffffffffu, mx1, 1));
        mx1 = fmaxf(mx1, __shfl_xor_sync(0xffffffffu, mx1, 2));
        float mn0 = fmaxf(m0, mx0), mn1 = fmaxf(m1, mx1);
        float sum0 = 0.f, sum1 = 0.f;
#pragma unroll
        for (int nt = 0; nt < 8; nt++) {
            s[nt][0] = __expf(s[nt][0] - mn0); sum0 += s[nt][0];
            s[nt][1] = __expf(s[nt][1] - mn0); sum0 += s[nt][1];
            s[nt][2] = __expf(s[nt][2] - mn1); sum1 += s[nt][2];
            s[nt][3] = __expf(s[nt][3] - mn1); sum1 += s[nt][3];
        }
        sum0 += __shfl_xor_sync(0xffffffffu, sum0, 1);
        sum0 += __shfl_xor_sync(0xffffffffu, sum0, 2);
        sum1 += __shfl_xor_sync(0xffffffffu, sum1, 1);
        sum1 += __shfl_xor_sync(0xffffffffu, sum1, 2);
        float c0f = __expf(m0 - mn0), c1f = __expf(m1 - mn1);
        lsum0 = lsum0 * c0f + sum0; lsum1 = lsum1 * c1f + sum1;
        m0 = mn0; m1 = mn1;
#pragma unroll
        for (int nt = 0; nt < 4; nt++) {
            o[nt][0] *= c0f; o[nt][1] *= c0f;
            o[nt][2] *= c1f; o[nt][3] *= c1f;
        }
        // P -> fp16 fragments (D layout == A layout for chained mma)
        unsigned pa[8], pb[8];
#pragma unroll
        for (int nt = 0; nt < 8; nt++) {
            pa[nt] = packf2(s[nt][0], s[nt][1]);
            pb[nt] = packf2(s[nt][2], s[nt][3]);
        }
        // O += P @ V  (V split hi+lo)
#pragma unroll
        for (int c = 0; c < 4; c++) {
            unsigned af[4] = { pa[2 * c], pb[2 * c], pa[2 * c + 1], pb[2 * c + 1] };
#pragma unroll
            for (int nt = 0; nt < 4; nt++) {
                int dr = 8 * nt + g;
                unsigned bh0 = ldu32(&Vh[dr][16 * c + 2 * tig]);
                unsigned bh1 = ldu32(&Vh[dr][16 * c + 8 + 2 * tig]);
                unsigned bl0 = ldu32(&Vl[dr][16 * c + 2 * tig]);
                unsigned bl1 = ldu32(&Vl[dr][16 * c + 8 + 2 * tig]);
                mma16816(o[nt], af, bh0, bh1);
                mma16816(o[nt], af, bl0, bl1);
            }
        }
    }

    float ri0 = 1.f / lsum0, ri1 = 1.f / lsum1;
#pragma unroll
    for (int nt = 0; nt < 4; nt++) {
        int d = h * 32 + 8 * nt + 2 * tig;
        float f0 = o[nt][0] * ri0, f1 = o[nt][1] * ri0;
        float f2 = o[nt][2] * ri1, f3 = o[nt][3] * ri1;
        __half h0, e0, h1, e1, h2, e2, h3, e3;
        splitf(f0, h0, e0); splitf(f1, h1, e1);
        splitf(f2, h2, e2); splitf(f3, h3, e3);
        int i0 = (b * LDIM + r0) * CDIM + d;
        int i1 = (b * LDIM + r0 + 8) * CDIM + d;
        *reinterpret_cast<__half2*>(g_oh + i0) = __halves2half2(h0, h1);
        *reinterpret_cast<__half2*>(g_ol + i0) = __halves2half2(e0, e1);
        *reinterpret_cast<__half2*>(g_oh + i1) = __halves2half2(h2, h3);
        *reinterpret_cast<__half2*>(g_ol + i1) = __halves2half2(e2, e3);
    }
}

// ---------------------------------------------------------------------------
// K3: FF GEMM, split-fp16, fused bias + transpose store.
// m=oc (64), n=l (64), k=c. grid(4,16,8) x 256 thr.
// ---------------------------------------------------------------------------
__global__ __launch_bounds__(256)
void ff_kernel(const float* __restrict__ ffw, const float* __restrict__ ffb,
               float* __restrict__ out) {
    __shared__ __half Fh[64][40], Fl[64][40];   // [oc][c]
    __shared__ __half Oh[64][40], Ol[64][40];   // [l][c]
    int b = blockIdx.z, l0 = blockIdx.y * 64, oc0 = blockIdx.x * 64;
    int tid = threadIdx.x, lane = tid & 31, w = tid >> 5;
    int g = lane >> 2, tig = lane & 3;
    int wm = (w & 3) * 16, wn = (w >> 2) * 32;
    const __half* ohp = g_oh + b * LDIM * CDIM;
    const __half* olp = g_ol + b * LDIM * CDIM;

    float acc[4][4];
#pragma unroll
    for (int i = 0; i < 4; i++)
#pragma unroll
        for (int j = 0; j < 4; j++) acc[i][j] = 0.f;

    for (int c0 = 0; c0 < 256; c0 += 32) {
        __syncthreads();
        for (int i = tid; i < 64 * 32; i += 256) {
            int nn = i & 63, cc = i >> 6;
            splitf(ffw[(c0 + cc) * 256 + oc0 + nn], Fh[nn][cc], Fl[nn][cc]);
        }
        for (int i = tid; i < 64 * 16; i += 256) {
            int ll = i >> 4, c2 = (i & 15) * 2;
            *reinterpret_cast<unsigned*>(&Oh[ll][c2]) =
                *reinterpret_cast<const unsigned*>(ohp + (l0 + ll) * CDIM + c0 + c2);
            *reinterpret_cast<unsigned*>(&Ol[ll][c2]) =
                *reinterpret_cast<const unsigned*>(olp + (l0 + ll) * CDIM + c0 + c2);
        }
        __syncthreads();
#pragma unroll
        for (int kc = 0; kc < 32; kc += 16) {
            unsigned ah[4], al[4];
            ah[0] = ldu32(&Fh[wm + g][kc + 2 * tig]);
            ah[1] = ldu32(&Fh[wm + g + 8][kc + 2 * tig]);
            ah[2] = ldu32(&Fh[wm + g][kc + 2 * tig + 8]);
            ah[3] = ldu32(&Fh[wm + g + 8][kc + 2 * tig + 8]);
            al[0] = ldu32(&Fl[wm + g][kc + 2 * tig]);
            al[1] = ldu32(&Fl[wm + g + 8][kc + 2 * tig]);
            al[2] = ldu32(&Fl[wm + g][kc + 2 * tig + 8]);
            al[3] = ldu32(&Fl[wm + g + 8][kc + 2 * tig + 8]);
#pragma unroll
            for (int nt = 0; nt < 4; nt++) {
                int lr = wn + 8 * nt + g;
                unsigned bh0 = ldu32(&Oh[lr][kc + 2 * tig]);
                unsigned bh1 = ldu32(&Oh[lr][kc + 2 * tig + 8]);
                unsigned bl0 = ldu32(&Ol[lr][kc + 2 * tig]);
                unsigned bl1 = ldu32(&Ol[lr][kc + 2 * tig + 8]);
                mma16816(acc[nt], ah, bh0, bh1);
                mma16816(acc[nt], ah, bl0, bl1);
                mma16816(acc[nt], al, bh0, bh1);
            }
        }
    }
#pragma unroll
    for (int nt = 0; nt < 4; nt++) {
        int lcol = l0 + wn + 8 * nt + 2 * tig;
        int ocr = oc0 + wm + g;
        float bv0 = ffb[ocr], bv1 = ffb[ocr + 8];
        float2 v0 = { acc[nt][0] + bv0, acc[nt][1] + bv0 };
        float2 v1 = { acc[nt][2] + bv1, acc[nt][3] + bv1 };
        *reinterpret_cast<float2*>(out + (b * 256 + ocr) * LDIM + lcol) = v0;
        *reinterpret_cast<float2*>(out + (b * 256 + ocr + 8) * LDIM + lcol) = v1;
    }
}

extern "C" void kernel_launch(void* const* d_in, const int* in_sizes, int n_in,
                              void* d_out, int out_size) {
    const float* x        = (const float*)d_in[0];
    const float* Qw       = (const float*)d_in[1];
    const float* Kw       = (const float*)d_in[2];
    const float* Vw       = (const float*)d_in[3];
    const float* ffw      = (const float*)d_in[4];
    const float* ffb      = (const float*)d_in[5];
    const float* rel_bias = (const float*)d_in[6];
    // d_in[7] = rel_idx : idx == (j - qi) + 1056, reproduced analytically.
    float* out = (float*)d_out;

    qkv_kernel<<<dim3(12, 16, 8), 256>>>(x, Qw, Kw, Vw);
    attn_kernel<<<dim3(16, 8, 8), 128>>>(rel_bias);
    ff_kernel<<<dim3(4, 16, 8), 256>>>(ffw, ffb, out);
}